// round 8
// baseline (speedup 1.0000x reference)
#include <cuda_runtime.h>
#include <cstdint>

#define HH 256
#define WW 256
#define NUM_CURVES 256
#define GPER 64                            /* 2 beziers * 32 samples */
#define NGAUSS (NUM_CURVES*GPER)           /* 16384 */
#define LOG2E 1.4426950408889634f
#define NTILE 1024                         /* 32 x 32 tiles of 8x8 px */
#define MASKW (NGAUSS/32)                  /* 512 words per tile */
#define NSEG 4
#define SEGW (MASKW/NSEG)                  /* 128 words per segment */
#define CAP 512                            /* staged survivors per chunk */
#define CUT 14.0f                          /* cutoff: a >= exp(-14) ~ 8.3e-7 */

// ---- static scratch ----
__device__ float4   d_gA[NGAUSS];            // mx, my, c0p, c1p
__device__ float4   d_gB[NGAUSS];            // c2p, log2(alpha), cr, cg
__device__ float    d_gCb[NGAUSS];           // cb
__device__ uint32_t d_mask[NTILE*MASKW];     // per-tile visibility bitmask
__device__ float4   d_part[NSEG*NTILE*64];   // per (seg,tile,px): rgb, T

// ---------------------------------------------------------------------------
// K1: one warp per curve. 256 blocks x 32 threads, no smem, no syncthreads.
// Each lane emits 2 gaussians (segment 0 and 1, same sample index).
// ---------------------------------------------------------------------------
__global__ void __launch_bounds__(32)
k_build(const float* __restrict__ ctrl,
        const float* __restrict__ fdc,
        const float* __restrict__ chol,
        const float* __restrict__ opac,
        const float* __restrict__ depth)
{
    int lane = threadIdx.x;
    int ci   = blockIdx.x;

    // --- stable depth rank: 8 compares per lane + butterfly reduce ---
    float d = __ldg(&depth[ci]);
    int partial = 0;
    #pragma unroll
    for (int jj = 0; jj < 8; ++jj) {
        int j = lane * 8 + jj;
        float dj = __ldg(&depth[j]);
        partial += (dj < d) || (dj == d && j < ci);
    }
    partial += __shfl_xor_sync(0xffffffffu, partial, 16);
    partial += __shfl_xor_sync(0xffffffffu, partial, 8);
    partial += __shfl_xor_sync(0xffffffffu, partial, 4);
    partial += __shfl_xor_sync(0xffffffffu, partial, 2);
    partial += __shfl_xor_sync(0xffffffffu, partial, 1);
    int rank = partial;

    // --- per-curve conic / color / extent (redundant on all lanes) ---
    float c0 = __ldg(&chol[3*ci+0]) + 0.5f;
    float c1 = __ldg(&chol[3*ci+1]);
    float c2 = __ldg(&chol[3*ci+2]) + 0.5f;
    float s00 = c0*c0;
    float s01 = c0*c1;
    float s11 = c1*c1 + c2*c2;
    float inv = 1.0f / (s00*s11 - s01*s01);
    float Ac =  s11*inv;
    float Bc = -s01*inv;
    float Cc =  s00*inv;

    float al  = 1.0f / (1.0f + expf(-__ldg(&opac[ci])));
    float l2a = log2f(al);
    float Q = fmaxf(2.0f * (CUT + logf(al)), 0.0f);
    float ex = sqrtf(Q * s00);
    float ey = sqrtf(Q * s11);

    float cpA = -0.5f*LOG2E*Ac;     // conic' terms
    float cpB = -LOG2E*Bc;
    float cpC = -0.5f*LOG2E*Cc;
    float colr = 1.0f/(1.0f+expf(-__ldg(&fdc[3*ci+0])));
    float colg = 1.0f/(1.0f+expf(-__ldg(&fdc[3*ci+1])));
    float colb = 1.0f/(1.0f+expf(-__ldg(&fdc[3*ci+2])));

    // --- Bernstein weights (shared by both segments: same sample s=lane) ---
    float tt = 0.007f + (float)lane * (0.986f / 31.0f);
    float u  = 1.0f - tt;
    float t2 = tt*tt, t3 = t2*tt, t4 = t2*t2, t5 = t4*tt;
    float u2 = u*u,   u3 = u2*u,  u4 = u2*u2, u5 = u4*u;
    float w0 = u5, w1 = 5.0f*tt*u4, w2 = 10.0f*t2*u3;
    float w3 = 10.0f*t3*u2, w4 = 5.0f*t4*u, w5 = t5;

    const float* cb_ = ctrl + ci * 20;

    #pragma unroll
    for (int k = 0; k < 2; ++k) {
        int i0 = k*5;
        int a0=i0, a1=i0+1, a2=i0+2, a3=i0+3, a4=i0+4, a5=(k ? 0 : 5);
        float px = w0*cb_[a0*2]   + w1*cb_[a1*2]   + w2*cb_[a2*2]
                 + w3*cb_[a3*2]   + w4*cb_[a4*2]   + w5*cb_[a5*2];
        float py = w0*cb_[a0*2+1] + w1*cb_[a1*2+1] + w2*cb_[a2*2+1]
                 + w3*cb_[a3*2+1] + w4*cb_[a4*2+1] + w5*cb_[a5*2+1];
        float mx = (tanhf(px)*0.5f + 0.5f) * (float)WW;
        float my = (tanhf(py)*0.5f + 0.5f) * (float)HH;

        int slot = rank*64 + k*32 + lane;
        d_gA[slot]  = make_float4(mx, my, cpA, cpB);
        d_gB[slot]  = make_float4(cpC, l2a, colr, colg);
        d_gCb[slot] = colb;

        // scatter visibility bit into 8x8-px tile masks
        int xlo = max(0,  (int)ceilf ((mx - ex - 8.0f) * 0.125f - 1e-4f));
        int xhi = min(31, (int)floorf((mx + ex)        * 0.125f + 1e-4f));
        int ylo = max(0,  (int)ceilf ((my - ey - 8.0f) * 0.125f - 1e-4f));
        int yhi = min(31, (int)floorf((my + ey)        * 0.125f + 1e-4f));
        if (xlo <= xhi && ylo <= yhi) {
            uint32_t bit  = 1u << (slot & 31);
            int      word = slot >> 5;
            for (int ty = ylo; ty <= yhi; ++ty)
                for (int tx = xlo; tx <= xhi; ++tx)
                    atomicOr(&d_mask[(ty*32 + tx)*MASKW + word], bit);
        }
    }
}

// ---------------------------------------------------------------------------
// K2: depth-segmented per-tile compositing.
// grid = (1024 tiles, 4 segments), 64 threads (1 px each, 8x8 tile).
// ---------------------------------------------------------------------------
__global__ void __launch_bounds__(64)
k_render()
{
    __shared__ float4 shA[CAP];
    __shared__ float4 shB[CAP];
    __shared__ float  shCb[CAP];
    __shared__ int    sW[2];

    int t    = threadIdx.x;
    int lane = t & 31;
    int wid  = t >> 5;
    int tile = blockIdx.x;
    int seg  = blockIdx.y;
    int tx8  = tile & 31;
    int ty8  = tile >> 5;
    float px = (float)(tx8*8 + (t & 7)) + 0.5f;
    float py = (float)(ty8*8 + (t >> 3)) + 0.5f;

    const uint32_t* mw = d_mask + (size_t)tile*MASKW + seg*SEGW + t*2;
    uint32_t m0 = mw[0];
    uint32_t m1 = mw[1];
    int c = __popc(m0) + __popc(m1);

    int incl = c;
    #pragma unroll
    for (int d = 1; d < 32; d <<= 1) {
        int v = __shfl_up_sync(0xffffffffu, incl, d);
        if (lane >= d) incl += v;
    }
    if (lane == 31) sW[wid] = incl;
    __syncthreads();
    int w0s = sW[0];
    int total = w0s + sW[1];
    int off = (wid ? w0s : 0) + incl - c;

    float T = 1.0f, cr = 0.0f, cg = 0.0f, cb = 0.0f;
    int slotBase = seg*SEGW*32 + t*64;

    for (int base = 0; base < total; base += CAP) {
        if (base > 0 && __syncthreads_and(T < 1e-4f)) break;
        int lim = min(base + CAP, total);

        if (off < lim && off + c > base) {
            int o = off;
            uint32_t mm = m0;
            int sb = slotBase;
            #pragma unroll
            for (int w = 0; w < 2; ++w) {
                while (mm) {
                    int b = __ffs(mm) - 1;
                    mm &= mm - 1;
                    if (o >= base && o < lim) {
                        int j = o - base;
                        int slot = sb + b;
                        shA[j]  = d_gA[slot];
                        shB[j]  = d_gB[slot];
                        shCb[j] = d_gCb[slot];
                    }
                    ++o;
                }
                mm = m1;
                sb = slotBase + 32;
            }
        }
        __syncthreads();

        int n = lim - base;
        int i = 0;
        while (i < n) {
            int ie = min(i + 64, n);
            if (T >= 1e-4f) {
                for (; i < ie; ++i) {
                    float4 A = shA[i];
                    float4 B = shB[i];
                    float dx = px - A.x;
                    float dy = py - A.y;
                    float e = B.y;                       // log2(alpha)
                    e = fmaf(A.z, dx*dx, e);
                    e = fmaf(A.w, dx*dy, e);
                    e = fmaf(B.x, dy*dy, e);
                    float a;
                    asm("ex2.approx.f32 %0, %1;" : "=f"(a) : "f"(e));
                    float w = a * T;
                    cr = fmaf(w, B.z, cr);
                    cg = fmaf(w, B.w, cg);
                    cb = fmaf(w, shCb[i], cb);
                    T  = fmaf(-a, T, T);
                }
            } else {
                i = ie;
            }
            if (__all_sync(0xffffffffu, T < 1e-4f)) i = n;
        }
        __syncthreads();
    }

    d_part[(seg*NTILE + tile)*64 + t] = make_float4(cr, cg, cb, T);
}

// ---------------------------------------------------------------------------
// K3: combine 4 segment partials per pixel, add background, clip, store.
// ---------------------------------------------------------------------------
__global__ void __launch_bounds__(64)
k_combine(const float* __restrict__ bgp, float* __restrict__ out)
{
    int t    = threadIdx.x;
    int tile = blockIdx.x;
    int tx8  = tile & 31;
    int ty8  = tile >> 5;

    float T = 1.0f, cr = 0.0f, cg = 0.0f, cb = 0.0f;
    #pragma unroll
    for (int s = 0; s < NSEG; ++s) {
        float4 p = d_part[(s*NTILE + tile)*64 + t];
        cr = fmaf(T, p.x, cr);
        cg = fmaf(T, p.y, cg);
        cb = fmaf(T, p.z, cb);
        T *= p.w;
    }

    float b0 = bgp[0], b1 = bgp[1], b2 = bgp[2];
    cr = fminf(fmaxf(fmaf(T, b0, cr), 0.0f), 1.0f);
    cg = fminf(fmaxf(fmaf(T, b1, cg), 0.0f), 1.0f);
    cb = fminf(fmaxf(fmaf(T, b2, cb), 0.0f), 1.0f);

    int x = tx8*8 + (t & 7);
    int y = ty8*8 + (t >> 3);
    int o = (y*WW + x) * 3;
    out[o+0] = cr;
    out[o+1] = cg;
    out[o+2] = cb;
}

// ---------------------------------------------------------------------------
extern "C" void kernel_launch(void* const* d_in, const int* in_sizes, int n_in,
                              void* d_out, int out_size)
{
    const float* ctrl  = (const float*)d_in[0];
    const float* fdc   = (const float*)d_in[1];
    const float* chol  = (const float*)d_in[2];
    const float* opac  = (const float*)d_in[3];
    const float* depth = (const float*)d_in[4];
    const float* bg    = (const float*)d_in[5];
    float* out = (float*)d_out;

    void* maskPtr = nullptr;
    cudaGetSymbolAddress(&maskPtr, d_mask);
    cudaMemsetAsync(maskPtr, 0, NTILE*MASKW*sizeof(uint32_t), 0);

    k_build<<<NUM_CURVES, 32>>>(ctrl, fdc, chol, opac, depth);
    k_render<<<dim3(NTILE, NSEG), 64>>>();
    k_combine<<<NTILE, 64>>>(bg, out);
}